// round 8
// baseline (speedup 1.0000x reference)
#include <cuda_runtime.h>
#include <cuda_fp16.h>
#include <cstdint>
#include <math.h>

#define D_MODEL 2048
#define N_EXP   64
#define TOP_K   8
#define SCALE   0.022097086912079608f
#define EPS     3.5e-5f
#define MAX_T   16384
#define CTA_TOK 64
#define NCHUNK  32            // 2048 / 64
#define WPITCH  160           // bytes per 64-half W smem row (bank-perfect LDS.64)
#define LROW    66

// ---- device globals (no allocations allowed) --------------------------------
// W planes stored FRAGMENT-PERMUTED: within each 16-half group g of a k-chunk,
// halves are ordered [k0,k1,k8,k9, k2,k3,k10,k11, k4,k5,k12,k13, k6,k7,k14,k15]
// so lane q4's mma B fragment {2q4,2q4+1,2q4+8,2q4+9} is 8 contiguous bytes.
__device__ __half gWhi[N_EXP * D_MODEL];
__device__ __half gWlo[N_EXP * D_MODEL];   // residual scaled by 2048
__device__ int    g_flag_count;
__device__ int    g_flags[MAX_T];

// ---- fp16 MMA ---------------------------------------------------------------
static __device__ __forceinline__ void mma16816(float* d, const uint32_t* a,
                                                uint32_t b0, uint32_t b1) {
    asm volatile(
        "mma.sync.aligned.m16n8k16.row.col.f32.f16.f16.f32 "
        "{%0,%1,%2,%3}, {%4,%5,%6,%7}, {%8,%9}, {%0,%1,%2,%3};"
        : "+f"(d[0]), "+f"(d[1]), "+f"(d[2]), "+f"(d[3])
        : "r"(a[0]), "r"(a[1]), "r"(a[2]), "r"(a[3]), "r"(b0), "r"(b1));
}

// ---------------------------------------------------------------------------
// Prep: split W into fp16 hi + fp16 lo*2048, written in fragment-permuted
// order (one 16-half group per thread). Zero flag counter.
// ---------------------------------------------------------------------------
__global__ void __launch_bounds__(256) prep_kernel(const float* __restrict__ W)
{
    if (blockIdx.x == 0 && threadIdx.x == 0) g_flag_count = 0;
    int g = blockIdx.x * 256 + threadIdx.x;       // 8192 groups of 16
    int base = g * 16;

    float f[16];
#pragma unroll
    for (int q = 0; q < 4; q++) {
        float4 v = *reinterpret_cast<const float4*>(W + base + q * 4);
        f[q * 4 + 0] = v.x; f[q * 4 + 1] = v.y;
        f[q * 4 + 2] = v.z; f[q * 4 + 3] = v.w;
    }
    // dst d -> src: pair p=d>>1, src = (p&1)*8 + (p>>1)*2 + (d&1)
    __half hi[16]; __half lo[16];
#pragma unroll
    for (int d = 0; d < 16; d++) {
        int p = d >> 1;
        int s = ((p & 1) << 3) + ((p >> 1) << 1) + (d & 1);
        float v = f[s];
        __half h = __float2half_rn(v);
        hi[d] = h;
        lo[d] = __float2half_rn((v - __half2float(h)) * 2048.0f);
    }
#pragma unroll
    for (int q = 0; q < 2; q++) {
        *reinterpret_cast<uint4*>(&gWhi[base + q * 8]) =
            *reinterpret_cast<const uint4*>(&hi[q * 8]);
        *reinterpret_cast<uint4*>(&gWlo[base + q * 8]) =
            *reinterpret_cast<const uint4*>(&lo[q * 8]);
    }
}

// ---------------------------------------------------------------------------
// Main: x(fp16) x [Whi,Wlo] HMMA, fused top-9 / flag / softmax.
// CTA = 256 thr / 8 warps = 4 token-groups x 2 expert-halves; CTA_TOK=64.
// Warp = 16 tokens x 32 experts (dh/dl 32 regs) -> 2 CTAs/SM, 4 warps/SMSP.
// W double-buffered in SMEM, pitch 160 (LDS.64 bank-perfect).
// ---------------------------------------------------------------------------
__global__ void __launch_bounds__(256, 2)
router_mma_kernel(const float* __restrict__ x, const float* __restrict__ bias,
                  float* __restrict__ out, int T)
{
    __shared__ __align__(16) char smW[2][2][64 * WPITCH];  // [buf][hi/lo] 40KB
    __shared__ float bias_sm[N_EXP];

    const int tid  = threadIdx.x;
    const int wid  = tid >> 5;
    const int lane = tid & 31;
    const int tg   = wid >> 1;          // token group 0..3
    const int eh   = wid & 1;           // expert half 0..1
    const int tokBase = blockIdx.x * CTA_TOK;
    const int wtok = tokBase + tg * 16;

    if (tid < N_EXP) bias_sm[tid] = bias[tid];

    const int n4 = lane >> 2;
    const int q4 = lane & 3;
    const int cp2 = q4 << 1;

    const float* xA = x + (size_t)(wtok + n4) * D_MODEL;
    const float* xB = x + (size_t)(wtok + n4 + 8) * D_MODEL;

    // W stage mapping: e = tid>>2, 16-half segment s = tid&3
    const int wge = (tid >> 2) * D_MODEL + (tid & 3) * 16;  // halves
    const int wse = (tid >> 2) * WPITCH + (tid & 3) * 32;   // bytes

    auto loadA = [&](int c, float2* f) {
#pragma unroll
        for (int ks = 0; ks < 4; ks++) {
            int kb = c * 64 + ks * 16;
            f[ks * 4 + 0] = *reinterpret_cast<const float2*>(xA + kb + cp2);
            f[ks * 4 + 1] = *reinterpret_cast<const float2*>(xB + kb + cp2);
            f[ks * 4 + 2] = *reinterpret_cast<const float2*>(xA + kb + cp2 + 8);
            f[ks * 4 + 3] = *reinterpret_cast<const float2*>(xB + kb + cp2 + 8);
        }
    };
    auto loadW = [&](int c, uint4* h, uint4* l) {
        h[0] = *reinterpret_cast<const uint4*>(&gWhi[wge + c * 64]);
        h[1] = *reinterpret_cast<const uint4*>(&gWhi[wge + c * 64 + 8]);
        l[0] = *reinterpret_cast<const uint4*>(&gWlo[wge + c * 64]);
        l[1] = *reinterpret_cast<const uint4*>(&gWlo[wge + c * 64 + 8]);
    };
    auto storeW = [&](int buf, const uint4* h, const uint4* l) {
        *reinterpret_cast<uint4*>(&smW[buf][0][wse])      = h[0];
        *reinterpret_cast<uint4*>(&smW[buf][0][wse + 16]) = h[1];
        *reinterpret_cast<uint4*>(&smW[buf][1][wse])      = l[0];
        *reinterpret_cast<uint4*>(&smW[buf][1][wse + 16]) = l[1];
    };

    // prologue
    float2 f[16];
    uint4 wh[2], wl[2];
    loadW(0, wh, wl);
    storeW(0, wh, wl);
    loadA(0, f);
    __syncthreads();

    float dh[4][4], dl[4][4];
#pragma unroll
    for (int j = 0; j < 4; j++)
#pragma unroll
        for (int q = 0; q < 4; q++) { dh[j][q] = 0.0f; dl[j][q] = 0.0f; }

    for (int c = 0; c < NCHUNK; c++) {
        const int buf = c & 1;

        uint32_t a[16];
#pragma unroll
        for (int i = 0; i < 16; i++) {
            __half2 h = __floats2half2_rn(f[i].x, f[i].y);
            a[i] = *reinterpret_cast<uint32_t*>(&h);
        }
        if (c + 1 < NCHUNK) {
            loadA(c + 1, f);
            loadW(c + 1, wh, wl);
        }

        const char* WH = smW[buf][0];
        const char* WL = smW[buf][1];
#pragma unroll
        for (int ks = 0; ks < 4; ks++) {
            const uint32_t cbase = (uint32_t)(ks * 32 + q4 * 8);
#pragma unroll
            for (int j = 0; j < 4; j++) {
                uint32_t ro = (uint32_t)((eh * 4 + j) * 8 + n4) * WPITCH + cbase;
                uint2 bh = *reinterpret_cast<const uint2*>(WH + ro);
                uint2 bl = *reinterpret_cast<const uint2*>(WL + ro);
                mma16816(dh[j], &a[ks * 4], bh.x, bh.y);
                mma16816(dl[j], &a[ks * 4], bl.x, bl.y);
            }
        }
        __syncthreads();
        if (c + 1 < NCHUNK) {
            storeW(buf ^ 1, wh, wl);
            __syncthreads();
        }
    }

    // ---- epilogue: spill combined logits to SMEM (aliases smW) -------------
    float* lw = reinterpret_cast<float*>(&smW[0][0][0]) + tg * 16 * LROW;
    const float invs = 1.0f / 2048.0f;
#pragma unroll
    for (int j = 0; j < 4; j++) {
        int col = eh * 32 + j * 8 + cp2;
        lw[n4 * LROW + col]           = dh[j][0] + dl[j][0] * invs;
        lw[n4 * LROW + col + 1]       = dh[j][1] + dl[j][1] * invs;
        lw[(n4 + 8) * LROW + col]     = dh[j][2] + dl[j][2] * invs;
        lw[(n4 + 8) * LROW + col + 1] = dh[j][3] + dl[j][3] * invs;
    }
    __syncthreads();

    if (eh == 0 && lane < 16) {
        const int tok = wtok + lane;
        const float* row = lw + lane * LROW;
        const float NEG = -3.0e38f;

        float val[9]; int idx[9];
#pragma unroll
        for (int j = 0; j < 9; j++) { val[j] = NEG; idx[j] = 0; }

#pragma unroll
        for (int e = 0; e < N_EXP; e++) {
            float cv = row[e] * SCALE + bias_sm[e];
            int   ci = e;
#pragma unroll
            for (int j = 0; j < 9; j++) {
                if (cv > val[j]) {
                    float tv = val[j]; val[j] = cv; cv = tv;
                    int   ti = idx[j]; idx[j] = ci; ci = ti;
                }
            }
        }

        float ming = val[0] - val[1];
#pragma unroll
        for (int j = 1; j < 8; j++) ming = fminf(ming, val[j] - val[j + 1]);

        float orig[TOP_K];
#pragma unroll
        for (int j = 0; j < TOP_K; j++) orig[j] = val[j] - bias_sm[idx[j]];
        float m = orig[0];
#pragma unroll
        for (int j = 1; j < TOP_K; j++) m = fmaxf(m, orig[j]);
        float ex[TOP_K], ssum = 0.0f;
#pragma unroll
        for (int j = 0; j < TOP_K; j++) { ex[j] = __expf(orig[j] - m); ssum += ex[j]; }
        float inv = 1.0f / ssum;

        float* wout = out + (size_t)tok * TOP_K;
        float* iout = out + (size_t)T * TOP_K + (size_t)tok * TOP_K;
#pragma unroll
        for (int j = 0; j < TOP_K; j++) { wout[j] = ex[j] * inv; iout[j] = (float)idx[j]; }

        if (ming < EPS) {
            int p = atomicAdd(&g_flag_count, 1);
            if (p < MAX_T) g_flags[p] = tok;
        }
    }
}

// ---------------------------------------------------------------------------
// Fixup (batched): 16 flagged tokens per CTA iteration; exact reference-
// matching blocked fp32 chain (panels of 512 = 4 staged K-chunks of 128,
// serial FFMA ascending, panels added ascending) + exact top-k/softmax.
// ---------------------------------------------------------------------------
#define FB 16
__global__ void __launch_bounds__(256) fixup_kernel(
    const float* __restrict__ x, const float* __restrict__ W,
    const float* __restrict__ bias, float* __restrict__ out, int T)
{
    __shared__ __align__(16) float Wp[128][68];
    __shared__ float Xp[FB][130];
    __shared__ float Lg[FB][66];
    __shared__ float bias_f[N_EXP];

    const int t = threadIdx.x;
    if (t < N_EXP) bias_f[t] = bias[t];

    int F = g_flag_count;
    if (F > MAX_T) F = MAX_T;
    if (F == 0) return;
    const int nb = (F + FB - 1) / FB;

    const int tk = t >> 4;
    const int e0 = (t & 15) * 4;
    const int xe = t & 63, xg = (t >> 6) * 32;
    const int stk = t >> 4, skk = (t & 15) * 8;

    for (int b = blockIdx.x; b < nb; b += gridDim.x) {
        float accT[4] = {0.f, 0.f, 0.f, 0.f};
        float accP[4] = {0.f, 0.f, 0.f, 0.f};

        for (int kc = 0; kc < 16; kc++) {
            __syncthreads();
            {
                int s2 = b * FB + stk;
                int gt = g_flags[(s2 < F) ? s2 : (F - 1)];
                const float* xp = x + (size_t)gt * D_MODEL + kc * 128 + skk;
                float4 v0 = *reinterpret_cast<const float4*>(xp);
                float4 v1 = *reinterpret_cast<const float4*>(xp + 4);
                Xp[stk][skk + 0] = v0.x; Xp[stk][skk + 1] = v0.y;
                Xp[stk][skk + 2] = v0.z; Xp[stk][skk + 3] = v0.w;
                Xp[stk][skk + 4] = v1.x; Xp[stk][skk + 5] = v1.y;
                Xp[stk][skk + 6] = v1.z; Xp[stk][skk + 7] = v1.w;
            }
#pragma unroll
            for (int u = 0; u < 32; u += 4) {
                float4 w = *reinterpret_cast<const float4*>(
                    W + (size_t)xe * D_MODEL + kc * 128 + xg + u);
                Wp[xg + u + 0][xe] = w.x;
                Wp[xg + u + 1][xe] = w.y;
                Wp[xg + u + 2][xe] = w.z;
                Wp[xg + u + 3][xe] = w.w;
            }
            __syncthreads();
#pragma unroll 4
            for (int k = 0; k < 128; k++) {
                float xv = Xp[tk][k];
                float4 wv = *reinterpret_cast<const float4*>(&Wp[k][e0]);
                accP[0] = __fmaf_rn(xv, wv.x, accP[0]);
                accP[1] = __fmaf_rn(xv, wv.y, accP[1]);
                accP[2] = __fmaf_rn(xv, wv.z, accP[2]);
                accP[3] = __fmaf_rn(xv, wv.w, accP[3]);
            }
            if ((kc & 3) == 3) {
#pragma unroll
                for (int q = 0; q < 4; q++) {
                    accT[q] = __fadd_rn(accT[q], accP[q]);
                    accP[q] = 0.0f;
                }
            }
        }
#pragma unroll
        for (int q = 0; q < 4; q++)
            Lg[tk][e0 + q] = __fmul_rn(accT[q], SCALE);
        __syncthreads();

        if (t < FB && b * FB + t < F) {
            const int tok = g_flags[b * FB + t];
            unsigned long long used = 0ull;
            int sel[TOP_K]; float sl[TOP_K];
            for (int k = 0; k < TOP_K; k++) {
                float best = -3.0e38f; int bi = 0;
                for (int e = 0; e < N_EXP; e++) {
                    if ((used >> e) & 1ull) continue;
                    float bv = __fadd_rn(Lg[t][e], bias_f[e]);
                    if (bv > best) { best = bv; bi = e; }
                }
                sel[k] = bi; sl[k] = Lg[t][bi];
                used |= (1ull << bi);
            }
            float m = sl[0];
            for (int k = 1; k < TOP_K; k++) m = fmaxf(m, sl[k]);
            float ex[TOP_K], s = 0.0f;
            for (int k = 0; k < TOP_K; k++) { ex[k] = __expf(sl[k] - m); s += ex[k]; }
            float inv = 1.0f / s;
            for (int k = 0; k < TOP_K; k++) {
                out[(size_t)tok * TOP_K + k] = ex[k] * inv;
                out[(size_t)T * TOP_K + (size_t)tok * TOP_K + k] = (float)sel[k];
            }
        }
    }
}

// ---------------------------------------------------------------------------
extern "C" void kernel_launch(void* const* d_in, const int* in_sizes, int n_in,
                              void* d_out, int out_size)
{
    const float* x    = (const float*)d_in[0];
    const float* W    = (const float*)d_in[1];
    const float* bias = (const float*)d_in[2];
    float* out        = (float*)d_out;

    int T = in_sizes[0] / D_MODEL;  // 16384

    prep_kernel<<<32, 256>>>(W);
    router_mma_kernel<<<T / CTA_TOK, 256>>>(x, bias, out, T);
    fixup_kernel<<<592, 256>>>(x, W, bias, out, T);
}

// round 9
// speedup vs baseline: 1.0879x; 1.0879x over previous
#include <cuda_runtime.h>
#include <cuda_fp16.h>
#include <cstdint>
#include <math.h>

#define D_MODEL 2048
#define N_EXP   64
#define TOP_K   8
#define SCALE   0.022097086912079608f
#define EPS     6e-5f
#define MAX_T   16384
#define CTA_TOK 64
#define NCHUNK  32            // 2048 / 64
#define WPITCH  160           // bytes per 64-half W smem row (bank-perfect LDS.64)
#define LROW    66

// ---- device globals (no allocations allowed) --------------------------------
// W plane stored FRAGMENT-PERMUTED: within each 16-half group of a k-chunk,
// halves are ordered [k0,k1,k8,k9, k2,k3,k10,k11, k4,k5,k12,k13, k6,k7,k14,k15]
// so lane q4's mma B fragment {2q4,2q4+1,2q4+8,2q4+9} is 8 contiguous bytes.
__device__ __half gWhi[N_EXP * D_MODEL];
__device__ int    g_flag_count;
__device__ int    g_flags[MAX_T];

// ---- fp16 MMA ---------------------------------------------------------------
static __device__ __forceinline__ void mma16816(float* d, const uint32_t* a,
                                                uint32_t b0, uint32_t b1) {
    asm volatile(
        "mma.sync.aligned.m16n8k16.row.col.f32.f16.f16.f32 "
        "{%0,%1,%2,%3}, {%4,%5,%6,%7}, {%8,%9}, {%0,%1,%2,%3};"
        : "+f"(d[0]), "+f"(d[1]), "+f"(d[2]), "+f"(d[3])
        : "r"(a[0]), "r"(a[1]), "r"(a[2]), "r"(a[3]), "r"(b0), "r"(b1));
}

// ---------------------------------------------------------------------------
// Prep: W (fp32) -> fp16 hi plane in fragment-permuted order. Zero flag count.
// ---------------------------------------------------------------------------
__global__ void __launch_bounds__(256) prep_kernel(const float* __restrict__ W)
{
    if (blockIdx.x == 0 && threadIdx.x == 0) g_flag_count = 0;
    int g = blockIdx.x * 256 + threadIdx.x;       // 8192 groups of 16
    int base = g * 16;

    float f[16];
#pragma unroll
    for (int q = 0; q < 4; q++) {
        float4 v = *reinterpret_cast<const float4*>(W + base + q * 4);
        f[q * 4 + 0] = v.x; f[q * 4 + 1] = v.y;
        f[q * 4 + 2] = v.z; f[q * 4 + 3] = v.w;
    }
    __half hi[16];
#pragma unroll
    for (int d = 0; d < 16; d++) {
        int p = d >> 1;
        int s = ((p & 1) << 3) + ((p >> 1) << 1) + (d & 1);
        hi[d] = __float2half_rn(f[s]);
    }
#pragma unroll
    for (int q = 0; q < 2; q++)
        *reinterpret_cast<uint4*>(&gWhi[base + q * 8]) =
            *reinterpret_cast<const uint4*>(&hi[q * 8]);
}

// ---------------------------------------------------------------------------
// Main: x(fp16) x Whi(fp16) single-pass HMMA, fused top-9 / flag / softmax.
// CTA = 256 thr / 8 warps = 4 token-groups x 2 expert-halves; CTA_TOK=64.
// Warp = 16 tokens x 32 experts; 2 CTAs/SM. W double-buffered, pitch 160.
// ---------------------------------------------------------------------------
__global__ void __launch_bounds__(256, 2)
router_mma_kernel(const float* __restrict__ x, const float* __restrict__ bias,
                  float* __restrict__ out, int T)
{
    __shared__ __align__(16) char smW[2][64 * WPITCH];  // 20.5 KB
    __shared__ float bias_sm[N_EXP];

    const int tid  = threadIdx.x;
    const int wid  = tid >> 5;
    const int lane = tid & 31;
    const int tg   = wid >> 1;          // token group 0..3
    const int eh   = wid & 1;           // expert half 0..1
    const int tokBase = blockIdx.x * CTA_TOK;
    const int wtok = tokBase + tg * 16;

    if (tid < N_EXP) bias_sm[tid] = bias[tid];

    const int n4 = lane >> 2;
    const int q4 = lane & 3;
    const int cp2 = q4 << 1;

    const float* xA = x + (size_t)(wtok + n4) * D_MODEL;
    const float* xB = x + (size_t)(wtok + n4 + 8) * D_MODEL;

    const int wge = (tid >> 2) * D_MODEL + (tid & 3) * 16;  // halves
    const int wse = (tid >> 2) * WPITCH + (tid & 3) * 32;   // bytes

    auto loadA = [&](int c, float2* f) {
#pragma unroll
        for (int ks = 0; ks < 4; ks++) {
            int kb = c * 64 + ks * 16;
            f[ks * 4 + 0] = *reinterpret_cast<const float2*>(xA + kb + cp2);
            f[ks * 4 + 1] = *reinterpret_cast<const float2*>(xB + kb + cp2);
            f[ks * 4 + 2] = *reinterpret_cast<const float2*>(xA + kb + cp2 + 8);
            f[ks * 4 + 3] = *reinterpret_cast<const float2*>(xB + kb + cp2 + 8);
        }
    };
    auto loadW = [&](int c, uint4* h) {
        h[0] = *reinterpret_cast<const uint4*>(&gWhi[wge + c * 64]);
        h[1] = *reinterpret_cast<const uint4*>(&gWhi[wge + c * 64 + 8]);
    };
    auto storeW = [&](int buf, const uint4* h) {
        *reinterpret_cast<uint4*>(&smW[buf][wse])      = h[0];
        *reinterpret_cast<uint4*>(&smW[buf][wse + 16]) = h[1];
    };

    // prologue
    float2 f[16];
    uint4 wh[2];
    loadW(0, wh);
    storeW(0, wh);
    loadA(0, f);
    __syncthreads();

    float dh[4][4];
#pragma unroll
    for (int j = 0; j < 4; j++)
#pragma unroll
        for (int q = 0; q < 4; q++) dh[j][q] = 0.0f;

    for (int c = 0; c < NCHUNK; c++) {
        const int buf = c & 1;

        uint32_t a[16];
#pragma unroll
        for (int i = 0; i < 16; i++) {
            __half2 h = __floats2half2_rn(f[i].x, f[i].y);
            a[i] = *reinterpret_cast<uint32_t*>(&h);
        }
        if (c + 1 < NCHUNK) {
            loadA(c + 1, f);
            loadW(c + 1, wh);
        }

        const char* WH = smW[buf];
#pragma unroll
        for (int ks = 0; ks < 4; ks++) {
            const uint32_t cbase = (uint32_t)(ks * 32 + q4 * 8);
#pragma unroll
            for (int j = 0; j < 4; j++) {
                uint32_t ro = (uint32_t)((eh * 4 + j) * 8 + n4) * WPITCH + cbase;
                uint2 bh = *reinterpret_cast<const uint2*>(WH + ro);
                mma16816(dh[j], &a[ks * 4], bh.x, bh.y);
            }
        }
        __syncthreads();
        if (c + 1 < NCHUNK) {
            storeW(buf ^ 1, wh);
            __syncthreads();
        }
    }

    // ---- epilogue: spill logits to SMEM (aliases smW) -----------------------
    float* lw = reinterpret_cast<float*>(&smW[0][0]) + tg * 16 * LROW;
#pragma unroll
    for (int j = 0; j < 4; j++) {
        int col = eh * 32 + j * 8 + cp2;
        lw[n4 * LROW + col]           = dh[j][0];
        lw[n4 * LROW + col + 1]       = dh[j][1];
        lw[(n4 + 8) * LROW + col]     = dh[j][2];
        lw[(n4 + 8) * LROW + col + 1] = dh[j][3];
    }
    __syncthreads();

    if (eh == 0 && lane < 16) {
        const int tok = wtok + lane;
        const float* row = lw + lane * LROW;
        const float NEG = -3.0e38f;

        float val[9]; int idx[9];
#pragma unroll
        for (int j = 0; j < 9; j++) { val[j] = NEG; idx[j] = 0; }

#pragma unroll
        for (int e = 0; e < N_EXP; e++) {
            float cv = row[e] * SCALE + bias_sm[e];
            int   ci = e;
#pragma unroll
            for (int j = 0; j < 9; j++) {
                if (cv > val[j]) {
                    float tv = val[j]; val[j] = cv; cv = tv;
                    int   ti = idx[j]; idx[j] = ci; ci = ti;
                }
            }
        }

        float ming = val[0] - val[1];
#pragma unroll
        for (int j = 1; j < 8; j++) ming = fminf(ming, val[j] - val[j + 1]);

        float orig[TOP_K];
#pragma unroll
        for (int j = 0; j < TOP_K; j++) orig[j] = val[j] - bias_sm[idx[j]];
        float m = orig[0];
#pragma unroll
        for (int j = 1; j < TOP_K; j++) m = fmaxf(m, orig[j]);
        float ex[TOP_K], ssum = 0.0f;
#pragma unroll
        for (int j = 0; j < TOP_K; j++) { ex[j] = __expf(orig[j] - m); ssum += ex[j]; }
        float inv = 1.0f / ssum;

        float* wout = out + (size_t)tok * TOP_K;
        float* iout = out + (size_t)T * TOP_K + (size_t)tok * TOP_K;
#pragma unroll
        for (int j = 0; j < TOP_K; j++) { wout[j] = ex[j] * inv; iout[j] = (float)idx[j]; }

        if (ming < EPS) {
            int p = atomicAdd(&g_flag_count, 1);
            if (p < MAX_T) g_flags[p] = tok;
        }
    }
}

// ---------------------------------------------------------------------------
// Fixup (batched): 16 flagged tokens per CTA iteration; exact reference-
// matching blocked fp32 chain (panels of 512 = 4 staged K-chunks of 128,
// serial FFMA ascending, panels added ascending) + exact top-k/softmax.
// ---------------------------------------------------------------------------
#define FB 16
__global__ void __launch_bounds__(256) fixup_kernel(
    const float* __restrict__ x, const float* __restrict__ W,
    const float* __restrict__ bias, float* __restrict__ out, int T)
{
    __shared__ __align__(16) float Wp[128][68];
    __shared__ float Xp[FB][130];
    __shared__ float Lg[FB][66];
    __shared__ float bias_f[N_EXP];

    const int t = threadIdx.x;
    if (t < N_EXP) bias_f[t] = bias[t];

    int F = g_flag_count;
    if (F > MAX_T) F = MAX_T;
    if (F == 0) return;
    const int nb = (F + FB - 1) / FB;

    const int tk = t >> 4;
    const int e0 = (t & 15) * 4;
    const int xe = t & 63, xg = (t >> 6) * 32;
    const int stk = t >> 4, skk = (t & 15) * 8;

    for (int b = blockIdx.x; b < nb; b += gridDim.x) {
        float accT[4] = {0.f, 0.f, 0.f, 0.f};
        float accP[4] = {0.f, 0.f, 0.f, 0.f};

        for (int kc = 0; kc < 16; kc++) {
            __syncthreads();
            {
                int s2 = b * FB + stk;
                int gt = g_flags[(s2 < F) ? s2 : (F - 1)];
                const float* xp = x + (size_t)gt * D_MODEL + kc * 128 + skk;
                float4 v0 = *reinterpret_cast<const float4*>(xp);
                float4 v1 = *reinterpret_cast<const float4*>(xp + 4);
                Xp[stk][skk + 0] = v0.x; Xp[stk][skk + 1] = v0.y;
                Xp[stk][skk + 2] = v0.z; Xp[stk][skk + 3] = v0.w;
                Xp[stk][skk + 4] = v1.x; Xp[stk][skk + 5] = v1.y;
                Xp[stk][skk + 6] = v1.z; Xp[stk][skk + 7] = v1.w;
            }
#pragma unroll
            for (int u = 0; u < 32; u += 4) {
                float4 w = *reinterpret_cast<const float4*>(
                    W + (size_t)xe * D_MODEL + kc * 128 + xg + u);
                Wp[xg + u + 0][xe] = w.x;
                Wp[xg + u + 1][xe] = w.y;
                Wp[xg + u + 2][xe] = w.z;
                Wp[xg + u + 3][xe] = w.w;
            }
            __syncthreads();
#pragma unroll 4
            for (int k = 0; k < 128; k++) {
                float xv = Xp[tk][k];
                float4 wv = *reinterpret_cast<const float4*>(&Wp[k][e0]);
                accP[0] = __fmaf_rn(xv, wv.x, accP[0]);
                accP[1] = __fmaf_rn(xv, wv.y, accP[1]);
                accP[2] = __fmaf_rn(xv, wv.z, accP[2]);
                accP[3] = __fmaf_rn(xv, wv.w, accP[3]);
            }
            if ((kc & 3) == 3) {
#pragma unroll
                for (int q = 0; q < 4; q++) {
                    accT[q] = __fadd_rn(accT[q], accP[q]);
                    accP[q] = 0.0f;
                }
            }
        }
#pragma unroll
        for (int q = 0; q < 4; q++)
            Lg[tk][e0 + q] = __fmul_rn(accT[q], SCALE);
        __syncthreads();

        if (t < FB && b * FB + t < F) {
            const int tok = g_flags[b * FB + t];
            unsigned long long used = 0ull;
            int sel[TOP_K]; float sl[TOP_K];
            for (int k = 0; k < TOP_K; k++) {
                float best = -3.0e38f; int bi = 0;
                for (int e = 0; e < N_EXP; e++) {
                    if ((used >> e) & 1ull) continue;
                    float bv = __fadd_rn(Lg[t][e], bias_f[e]);
                    if (bv > best) { best = bv; bi = e; }
                }
                sel[k] = bi; sl[k] = Lg[t][bi];
                used |= (1ull << bi);
            }
            float m = sl[0];
            for (int k = 1; k < TOP_K; k++) m = fmaxf(m, sl[k]);
            float ex[TOP_K], s = 0.0f;
            for (int k = 0; k < TOP_K; k++) { ex[k] = __expf(sl[k] - m); s += ex[k]; }
            float inv = 1.0f / s;
            for (int k = 0; k < TOP_K; k++) {
                out[(size_t)tok * TOP_K + k] = ex[k] * inv;
                out[(size_t)T * TOP_K + (size_t)tok * TOP_K + k] = (float)sel[k];
            }
        }
    }
}

// ---------------------------------------------------------------------------
extern "C" void kernel_launch(void* const* d_in, const int* in_sizes, int n_in,
                              void* d_out, int out_size)
{
    const float* x    = (const float*)d_in[0];
    const float* W    = (const float*)d_in[1];
    const float* bias = (const float*)d_in[2];
    float* out        = (float*)d_out;

    int T = in_sizes[0] / D_MODEL;  // 16384

    prep_kernel<<<32, 256>>>(W);
    router_mma_kernel<<<T / CTA_TOK, 256>>>(x, bias, out, T);
    fixup_kernel<<<592, 256>>>(x, W, bias, out, T);
}

// round 10
// speedup vs baseline: 1.1967x; 1.1000x over previous
#include <cuda_runtime.h>
#include <cuda_fp16.h>
#include <cstdint>
#include <math.h>

#define D_MODEL 2048
#define N_EXP   64
#define TOP_K   8
#define SCALE   0.022097086912079608f
#define EPS     6e-5f
#define MAX_T   16384
#define CTA_TOK 64
#define NCHUNK  32            // 2048 / 64
#define WPITCH  160           // bytes per 64-half W smem row (bank-perfect LDS.64)
#define TPITCH  528           // bytes per 16x16 A-fragment tile (bank-rotated)
#define LROW    66

// ---- device globals (no allocations allowed) --------------------------------
// W plane stored FRAGMENT-PERMUTED (proven in R8/R9): within each 16-half
// group, order [k0,k1,k8,k9, k2,k3,k10,k11, k4,k5,k12,k13, k6,k7,k14,k15].
__device__ __half gWhi[N_EXP * D_MODEL];
__device__ int    g_flag_count;
__device__ int    g_flags[MAX_T];

// ---- fp16 MMA ---------------------------------------------------------------
static __device__ __forceinline__ void mma16816(float* d, const uint32_t* a,
                                                uint32_t b0, uint32_t b1) {
    asm volatile(
        "mma.sync.aligned.m16n8k16.row.col.f32.f16.f16.f32 "
        "{%0,%1,%2,%3}, {%4,%5,%6,%7}, {%8,%9}, {%0,%1,%2,%3};"
        : "+f"(d[0]), "+f"(d[1]), "+f"(d[2]), "+f"(d[3])
        : "r"(a[0]), "r"(a[1]), "r"(a[2]), "r"(a[3]), "r"(b0), "r"(b1));
}

// ---------------------------------------------------------------------------
// Prep: W (fp32) -> fp16 plane in fragment-permuted order. Zero flag count.
// ---------------------------------------------------------------------------
__global__ void __launch_bounds__(256) prep_kernel(const float* __restrict__ W)
{
    if (blockIdx.x == 0 && threadIdx.x == 0) g_flag_count = 0;
    int g = blockIdx.x * 256 + threadIdx.x;       // 8192 groups of 16
    int base = g * 16;

    float f[16];
#pragma unroll
    for (int q = 0; q < 4; q++) {
        float4 v = *reinterpret_cast<const float4*>(W + base + q * 4);
        f[q * 4 + 0] = v.x; f[q * 4 + 1] = v.y;
        f[q * 4 + 2] = v.z; f[q * 4 + 3] = v.w;
    }
    __half hi[16];
#pragma unroll
    for (int d = 0; d < 16; d++) {
        int p = d >> 1;
        int s = ((p & 1) << 3) + ((p >> 1) << 1) + (d & 1);
        hi[d] = __float2half_rn(f[s]);
    }
#pragma unroll
    for (int q = 0; q < 2; q++)
        *reinterpret_cast<uint4*>(&gWhi[base + q * 8]) =
            *reinterpret_cast<const uint4*>(&hi[q * 8]);
}

// ---------------------------------------------------------------------------
// Main: x(fp16) x Whi(fp16) HMMA, A tile staged in SMEM fragment-permuted
// (coalesced LDG.128, one LDS.128 per A fragment), fused top-9/flag/softmax.
// CTA = 256 thr / 8 warps = 4 token-groups x 2 expert-halves; CTA_TOK=64.
// ---------------------------------------------------------------------------
#define SM_A(s)  ((s) * (16 * TPITCH))                 // 2 x 8448
#define SM_W(s)  (2 * 16 * TPITCH + (s) * (64 * WPITCH))
#define SM_BIAS  (2 * 16 * TPITCH + 2 * 64 * WPITCH)
#define SM_TOT   (SM_BIAS + 256)

__global__ void __launch_bounds__(256, 2)
router_mma_kernel(const float* __restrict__ x, const float* __restrict__ bias,
                  float* __restrict__ out, int T)
{
    __shared__ __align__(16) char sm[SM_TOT];

    const int tid  = threadIdx.x;
    const int wid  = tid >> 5;
    const int lane = tid & 31;
    const int tg   = wid >> 1;          // token group 0..3
    const int eh   = wid & 1;           // expert half 0..1
    const int tokBase = blockIdx.x * CTA_TOK;
    const int wtok = tokBase + tg * 16;

    float* bias_sm = reinterpret_cast<float*>(sm + SM_BIAS);
    if (tid < N_EXP) bias_sm[tid] = bias[tid];

    const int n4 = lane >> 2;
    const int q4 = lane & 3;
    const int cp2 = q4 << 1;

    // ---- A writer mapping: 4 float4 per thread, coalesced ------------------
    // u = tid + 256*j : r = u>>4 (token row 0..63), k0 = (u&15)*4
    int arow[4], adst0[4], adst1[4];
#pragma unroll
    for (int j = 0; j < 4; j++) {
        int u  = tid + 256 * j;
        int r  = u >> 4;
        int k0 = (u & 15) * 4;
        int tgw = r >> 4, rr = r & 15, rA = rr & 7, hifl = rr >> 3;
        int ks = k0 >> 4, kk = k0 & 15, khi = kk >> 3, qa = (kk & 7) >> 1;
        arow[j]  = r;
        int tbase = (tgw * 4 + ks) * TPITCH + (hifl + khi * 2) * 4;
        adst0[j] = tbase + (rA * 4 + qa) * 16;       // pair (k0,k0+1)
        adst1[j] = tbase + (rA * 4 + qa + 1) * 16;   // pair (k0+2,k0+3)
    }
    const int ak0_0 = (tid & 15) * 4;

    // ---- W stage mapping: e = tid>>2, 16-half segment s = tid&3 ------------
    const int wge = (tid >> 2) * D_MODEL + (tid & 3) * 16;  // halves
    const int wse = (tid >> 2) * WPITCH + (tid & 3) * 32;   // bytes

    auto loadA = [&](int c, float4* av) {
#pragma unroll
        for (int j = 0; j < 4; j++)
            av[j] = *reinterpret_cast<const float4*>(
                x + (size_t)(tokBase + arow[j]) * D_MODEL + c * 64 + ak0_0);
    };
    auto storeA = [&](int s, const float4* av) {
#pragma unroll
        for (int j = 0; j < 4; j++) {
            __half2 h01 = __floats2half2_rn(av[j].x, av[j].y);
            __half2 h23 = __floats2half2_rn(av[j].z, av[j].w);
            *reinterpret_cast<uint32_t*>(sm + SM_A(s) + adst0[j]) =
                *reinterpret_cast<uint32_t*>(&h01);
            *reinterpret_cast<uint32_t*>(sm + SM_A(s) + adst1[j]) =
                *reinterpret_cast<uint32_t*>(&h23);
        }
    };
    auto loadW = [&](int c, uint4* h) {
        h[0] = *reinterpret_cast<const uint4*>(&gWhi[wge + c * 64]);
        h[1] = *reinterpret_cast<const uint4*>(&gWhi[wge + c * 64 + 8]);
    };
    auto storeW = [&](int s, const uint4* h) {
        *reinterpret_cast<uint4*>(&sm[SM_W(s) + wse])      = h[0];
        *reinterpret_cast<uint4*>(&sm[SM_W(s) + wse + 16]) = h[1];
    };

    // prologue: stage chunk 0
    float4 av[4];
    uint4  wh[2];
    loadA(0, av);
    loadW(0, wh);
    storeA(0, av);
    storeW(0, wh);
    __syncthreads();

    float dh[4][4];
#pragma unroll
    for (int j = 0; j < 4; j++)
#pragma unroll
        for (int q = 0; q < 4; q++) dh[j][q] = 0.0f;

    for (int c = 0; c < NCHUNK; c++) {
        const int buf = c & 1;

        // prefetch next chunk into regs (covered by MMA section)
        if (c + 1 < NCHUNK) {
            loadA(c + 1, av);
            loadW(c + 1, wh);
        }

        const char* AS = sm + SM_A(buf);
        const char* WH = sm + SM_W(buf);
#pragma unroll
        for (int ks = 0; ks < 4; ks++) {
            // A fragment: one LDS.128 per lane
            uint4 af = *reinterpret_cast<const uint4*>(
                AS + (tg * 4 + ks) * TPITCH + lane * 16);
            uint32_t a[4] = {af.x, af.y, af.z, af.w};
            const uint32_t cbase = (uint32_t)(ks * 32 + q4 * 8);
#pragma unroll
            for (int j = 0; j < 4; j++) {
                uint32_t ro = (uint32_t)((eh * 4 + j) * 8 + n4) * WPITCH + cbase;
                uint2 bh = *reinterpret_cast<const uint2*>(WH + ro);
                mma16816(dh[j], a, bh.x, bh.y);
            }
        }
        __syncthreads();
        if (c + 1 < NCHUNK) {
            storeA(buf ^ 1, av);
            storeW(buf ^ 1, wh);
            __syncthreads();
        }
    }

    // ---- epilogue: spill logits into W region, per-lane top-9 --------------
    float* lw = reinterpret_cast<float*>(sm + SM_W(0)) + tg * 16 * LROW;
#pragma unroll
    for (int j = 0; j < 4; j++) {
        int col = eh * 32 + j * 8 + cp2;
        lw[n4 * LROW + col]           = dh[j][0];
        lw[n4 * LROW + col + 1]       = dh[j][1];
        lw[(n4 + 8) * LROW + col]     = dh[j][2];
        lw[(n4 + 8) * LROW + col + 1] = dh[j][3];
    }
    __syncthreads();

    if (eh == 0 && lane < 16) {
        const int tok = wtok + lane;
        const float* row = lw + lane * LROW;
        const float NEG = -3.0e38f;

        float val[9]; int idx[9];
#pragma unroll
        for (int j = 0; j < 9; j++) { val[j] = NEG; idx[j] = 0; }

#pragma unroll
        for (int e = 0; e < N_EXP; e++) {
            float cv = row[e] * SCALE + bias_sm[e];
            int   ci = e;
#pragma unroll
            for (int j = 0; j < 9; j++) {
                if (cv > val[j]) {
                    float tv = val[j]; val[j] = cv; cv = tv;
                    int   ti = idx[j]; idx[j] = ci; ci = ti;
                }
            }
        }

        float ming = val[0] - val[1];
#pragma unroll
        for (int j = 1; j < 8; j++) ming = fminf(ming, val[j] - val[j + 1]);

        float orig[TOP_K];
#pragma unroll
        for (int j = 0; j < TOP_K; j++) orig[j] = val[j] - bias_sm[idx[j]];
        float m = orig[0];
#pragma unroll
        for (int j = 1; j < TOP_K; j++) m = fmaxf(m, orig[j]);
        float ex[TOP_K], ssum = 0.0f;
#pragma unroll
        for (int j = 0; j < TOP_K; j++) { ex[j] = __expf(orig[j] - m); ssum += ex[j]; }
        float inv = 1.0f / ssum;

        float* wout = out + (size_t)tok * TOP_K;
        float* iout = out + (size_t)T * TOP_K + (size_t)tok * TOP_K;
#pragma unroll
        for (int j = 0; j < TOP_K; j++) { wout[j] = ex[j] * inv; iout[j] = (float)idx[j]; }

        if (ming < EPS) {
            int p = atomicAdd(&g_flag_count, 1);
            if (p < MAX_T) g_flags[p] = tok;
        }
    }
}

// ---------------------------------------------------------------------------
// Fixup (batched, proven): 16 flagged tokens per CTA iteration; exact
// reference-matching blocked fp32 chain (4 panels of 512, serial FFMA
// ascending, panels added ascending) + exact top-k/softmax.
// ---------------------------------------------------------------------------
#define FB 16
__global__ void __launch_bounds__(256) fixup_kernel(
    const float* __restrict__ x, const float* __restrict__ W,
    const float* __restrict__ bias, float* __restrict__ out, int T)
{
    __shared__ __align__(16) float Wp[128][68];
    __shared__ float Xp[FB][130];
    __shared__ float Lg[FB][66];
    __shared__ float bias_f[N_EXP];

    const int t = threadIdx.x;
    if (t < N_EXP) bias_f[t] = bias[t];

    int F = g_flag_count;
    if (F > MAX_T) F = MAX_T;
    if (F == 0) return;
    const int nb = (F + FB - 1) / FB;

    const int tk = t >> 4;
    const int e0 = (t & 15) * 4;
    const int xe = t & 63, xg = (t >> 6) * 32;
    const int stk = t >> 4, skk = (t & 15) * 8;

    for (int b = blockIdx.x; b < nb; b += gridDim.x) {
        float accT[4] = {0.f, 0.f, 0.f, 0.f};
        float accP[4] = {0.f, 0.f, 0.f, 0.f};

        for (int kc = 0; kc < 16; kc++) {
            __syncthreads();
            {
                int s2 = b * FB + stk;
                int gt = g_flags[(s2 < F) ? s2 : (F - 1)];
                const float* xp = x + (size_t)gt * D_MODEL + kc * 128 + skk;
                float4 v0 = *reinterpret_cast<const float4*>(xp);
                float4 v1 = *reinterpret_cast<const float4*>(xp + 4);
                Xp[stk][skk + 0] = v0.x; Xp[stk][skk + 1] = v0.y;
                Xp[stk][skk + 2] = v0.z; Xp[stk][skk + 3] = v0.w;
                Xp[stk][skk + 4] = v1.x; Xp[stk][skk + 5] = v1.y;
                Xp[stk][skk + 6] = v1.z; Xp[stk][skk + 7] = v1.w;
            }
#pragma unroll
            for (int u = 0; u < 32; u += 4) {
                float4 w = *reinterpret_cast<const float4*>(
                    W + (size_t)xe * D_MODEL + kc * 128 + xg + u);
                Wp[xg + u + 0][xe] = w.x;
                Wp[xg + u + 1][xe] = w.y;
                Wp[xg + u + 2][xe] = w.z;
                Wp[xg + u + 3][xe] = w.w;
            }
            __syncthreads();
#pragma unroll 4
            for (int k = 0; k < 128; k++) {
                float xv = Xp[tk][k];
                float4 wv = *reinterpret_cast<const float4*>(&Wp[k][e0]);
                accP[0] = __fmaf_rn(xv, wv.x, accP[0]);
                accP[1] = __fmaf_rn(xv, wv.y, accP[1]);
                accP[2] = __fmaf_rn(xv, wv.z, accP[2]);
                accP[3] = __fmaf_rn(xv, wv.w, accP[3]);
            }
            if ((kc & 3) == 3) {
#pragma unroll
                for (int q = 0; q < 4; q++) {
                    accT[q] = __fadd_rn(accT[q], accP[q]);
                    accP[q] = 0.0f;
                }
            }
        }
#pragma unroll
        for (int q = 0; q < 4; q++)
            Lg[tk][e0 + q] = __fmul_rn(accT[q], SCALE);
        __syncthreads();

        if (t < FB && b * FB + t < F) {
            const int tok = g_flags[b * FB + t];
            unsigned long long used = 0ull;
            int sel[TOP_K]; float sl[TOP_K];
            for (int k = 0; k < TOP_K; k++) {
                float best = -3.0e38f; int bi = 0;
                for (int e = 0; e < N_EXP; e++) {
                    if ((used >> e) & 1ull) continue;
                    float bv = __fadd_rn(Lg[t][e], bias_f[e]);
                    if (bv > best) { best = bv; bi = e; }
                }
                sel[k] = bi; sl[k] = Lg[t][bi];
                used |= (1ull << bi);
            }
            float m = sl[0];
            for (int k = 1; k < TOP_K; k++) m = fmaxf(m, sl[k]);
            float ex[TOP_K], s = 0.0f;
            for (int k = 0; k < TOP_K; k++) { ex[k] = __expf(sl[k] - m); s += ex[k]; }
            float inv = 1.0f / s;
            for (int k = 0; k < TOP_K; k++) {
                out[(size_t)tok * TOP_K + k] = ex[k] * inv;
                out[(size_t)T * TOP_K + (size_t)tok * TOP_K + k] = (float)sel[k];
            }
        }
    }
}

// ---------------------------------------------------------------------------
extern "C" void kernel_launch(void* const* d_in, const int* in_sizes, int n_in,
                              void* d_out, int out_size)
{
    const float* x    = (const float*)d_in[0];
    const float* W    = (const float*)d_in[1];
    const float* bias = (const float*)d_in[2];
    float* out        = (float*)d_out;

    int T = in_sizes[0] / D_MODEL;  // 16384

    prep_kernel<<<32, 256>>>(W);
    router_mma_kernel<<<T / CTA_TOK, 256>>>(x, bias, out, T);
    fixup_kernel<<<592, 256>>>(x, W, bias, out, T);
}